// round 4
// baseline (speedup 1.0000x reference)
#include <cuda_runtime.h>
#include <math.h>

#define T_LEN 1024
#define DX    32
#define DZ    64
#define DY    256
#define BB    4
#define NCTA  128
#define NTHR  512
#define ALPHA 0.125f
#define HPAD  8                  // shB row pad: makes GEMM1 STS banks bijective

// Packed fp32x2 FMA (Blackwell sm_103a): d = a*b + c elementwise on 64-bit pairs.
__device__ __forceinline__ float2 ffma2(float2 a, float2 b, float2 c) {
    unsigned long long au = *reinterpret_cast<unsigned long long*>(&a);
    unsigned long long bu = *reinterpret_cast<unsigned long long*>(&b);
    unsigned long long cu = *reinterpret_cast<unsigned long long*>(&c);
    unsigned long long du;
    asm("fma.rn.f32x2 %0, %1, %2, %3;" : "=l"(du) : "l"(au), "l"(bu), "l"(cu));
    return *reinterpret_cast<float2*>(&du);
}

__global__ __launch_bounds__(NTHR, 1)
void plrnn_kernel(const float* __restrict__ X,
                  const float* __restrict__ A,
                  const float* __restrict__ W1,   // (dz, dy) row-major
                  const float* __restrict__ W2,   // (dy, dz) row-major
                  const float* __restrict__ h1,
                  const float* __restrict__ h2,
                  float* __restrict__ out)        // (B, T, dx)
{
    __shared__ float szfB[BB][DZ];           // [b][k] zf
    __shared__ float shB [BB][DY + HPAD];    // [b][y] hidden (padded rows)
    __shared__ float sPart[16][BB][DZ];      // [ychunk][b][z] partials

    const int t = threadIdx.x;

    // state / reduce role (threads 0..255 own one (b,z) state each)
    const int z  = t & 63;
    const int b  = (t >> 6) & 3;
    const int bg = blockIdx.x * BB + b;

    // GEMM1 role: 2 consecutive y, one quarter-k, all 4 batches
    const int q2 = t >> 2;                   // 0..127
    const int y0 = 2 * q2;
    const int kq = t & 3;                    // quarter-k id; shfl quad = lanes t^1,t^2

    // GEMM2 role: 2 consecutive z, one 16-wide y chunk, all 4 batches
    const int zg0 = 2 * (t & 31);
    const int g16 = t >> 5;                  // 0..15

    // ---- weights in registers, natural (even,odd) float2 pairs ----
    float2 w2a[8], w2b[8];                   // W2 rows y0/y0+1, k in [16*kq, +16)
#pragma unroll
    for (int p = 0; p < 8; ++p) {
        w2a[p] = *reinterpret_cast<const float2*>(&W2[(size_t)y0 * DZ + 16 * kq + 2 * p]);
        w2b[p] = *reinterpret_cast<const float2*>(&W2[(size_t)(y0 + 1) * DZ + 16 * kq + 2 * p]);
    }
    float2 w1a[8], w1b[8];                   // W1 rows zg0/zg0+1, y in [16*g16, +16)
#pragma unroll
    for (int p = 0; p < 8; ++p) {
        w1a[p] = *reinterpret_cast<const float2*>(&W1[(size_t)zg0 * DY + 16 * g16 + 2 * p]);
        w1b[p] = *reinterpret_cast<const float2*>(&W1[(size_t)(zg0 + 1) * DY + 16 * g16 + 2 * p]);
    }
    const float2 h2v = *reinterpret_cast<const float2*>(&h2[y0]);
    const float  Az  = A[z];
    const float  h1z = h1[z];

    const float* Xb = X   + (size_t)bg * T_LEN * DX;
    float*       Ob = out + (size_t)bg * T_LEN * DX;

    // ---- z0 (threads < 256 own state): first dx dims forced alpha=1, rest 0 ----
    float zcur = 0.0f, x_next = 0.0f;
    if (t < 256 && z < DX) {
        float x0 = Xb[z];
        zcur   = (x0 != x0) ? 0.0f : x0;     // NaN -> keep 0
        x_next = x0;                          // step-0 forcing reuses X[:,0]
    }

    for (int step = 0; step < T_LEN; ++step) {
        // ---- phase 0: teacher forcing + publish zf (state owners only) ----
        if (t < 256) {
            float zf;
            if (z < DX) {
                float x = x_next;
                zf = (x != x) ? zcur : fmaf(ALPHA, x, (1.0f - ALPHA) * zcur);
                if (step + 1 < T_LEN)
                    x_next = Xb[(size_t)(step + 1) * DX + z];
            } else {
                zf = zcur;
            }
            zcur = zf;                        // zf is the value A*zf uses later
            szfB[b][z] = zf;
        }
        __syncthreads();                      // B1: zf ready

        // ---- GEMM1 (quarter-k split): partials for (y0,y0+1) x 4 batches ----
        {
            float2 a0[BB], a1[BB];
#pragma unroll
            for (int bb = 0; bb < BB; ++bb) { a0[bb] = make_float2(0.f, 0.f);
                                              a1[bb] = make_float2(0.f, 0.f); }
#pragma unroll
            for (int j = 0; j < 4; ++j) {
#pragma unroll
                for (int bb = 0; bb < BB; ++bb) {
                    float4 v = *reinterpret_cast<const float4*>(&szfB[bb][16 * kq + 4 * j]);
                    float2 lo = make_float2(v.x, v.y), hi = make_float2(v.z, v.w);
                    a0[bb] = ffma2(w2a[2 * j],     lo, a0[bb]);
                    a0[bb] = ffma2(w2a[2 * j + 1], hi, a0[bb]);
                    a1[bb] = ffma2(w2b[2 * j],     lo, a1[bb]);
                    a1[bb] = ffma2(w2b[2 * j + 1], hi, a1[bb]);
                }
            }
            // combine the 4 k-quarters within the lane quad
            float s0[BB], s1[BB];
#pragma unroll
            for (int bb = 0; bb < BB; ++bb) {
                s0[bb] = a0[bb].x + a0[bb].y;
                s1[bb] = a1[bb].x + a1[bb].y;
                s0[bb] += __shfl_xor_sync(0xffffffffu, s0[bb], 1);
                s1[bb] += __shfl_xor_sync(0xffffffffu, s1[bb], 1);
                s0[bb] += __shfl_xor_sync(0xffffffffu, s0[bb], 2);
                s1[bb] += __shfl_xor_sync(0xffffffffu, s1[bb], 2);
            }
            // lane kq stores batch kq (banks 8*bb + 2*q2 mod 32: conflict-free)
            float2 hv;
            hv.x = fmaxf(s0[kq] + h2v.x, 0.0f);
            hv.y = fmaxf(s1[kq] + h2v.y, 0.0f);
            *reinterpret_cast<float2*>(&shB[kq][y0]) = hv;
        }
        __syncthreads();                      // B2: hidden ready

        // ---- GEMM2: part[g16][b][zg0..+1] over 16-wide y chunk ----
        {
            float2 c0[BB], c1[BB];
#pragma unroll
            for (int bb = 0; bb < BB; ++bb) { c0[bb] = make_float2(0.f, 0.f);
                                              c1[bb] = make_float2(0.f, 0.f); }
#pragma unroll
            for (int yq = 0; yq < 4; ++yq) {
#pragma unroll
                for (int bb = 0; bb < BB; ++bb) {
                    float4 hv = *reinterpret_cast<const float4*>(&shB[bb][16 * g16 + 4 * yq]);
                    float2 lo = make_float2(hv.x, hv.y), hi = make_float2(hv.z, hv.w);
                    c0[bb] = ffma2(w1a[2 * yq],     lo, c0[bb]);
                    c0[bb] = ffma2(w1a[2 * yq + 1], hi, c0[bb]);
                    c1[bb] = ffma2(w1b[2 * yq],     lo, c1[bb]);
                    c1[bb] = ffma2(w1b[2 * yq + 1], hi, c1[bb]);
                }
            }
#pragma unroll
            for (int bb = 0; bb < BB; ++bb) {
                float2 pr;
                pr.x = c0[bb].x + c0[bb].y;   // z = zg0
                pr.y = c1[bb].x + c1[bb].y;   // z = zg0+1
                *reinterpret_cast<float2*>(&sPart[g16][bb][zg0]) = pr;
            }
        }
        __syncthreads();                      // B3: partials ready

        // ---- reduce 16 chunks + state update + output (state owners) ----
        if (t < 256) {
            float s = 0.0f;
#pragma unroll
            for (int g = 0; g < 16; ++g) s += sPart[g][b][z];
            float znew = fmaf(Az, zcur, s + h1z);
            zcur = znew;
            if (z < DX)
                Ob[(size_t)step * DX + z] = znew;   // coalesced
        }
    }
}

extern "C" void kernel_launch(void* const* d_in, const int* in_sizes, int n_in,
                              void* d_out, int out_size)
{
    const float* X  = (const float*)d_in[0];   // (512, 1024, 32)
    const float* A  = (const float*)d_in[1];   // (64,)
    const float* W1 = (const float*)d_in[2];   // (64, 256)
    const float* W2 = (const float*)d_in[3];   // (256, 64)
    const float* h1 = (const float*)d_in[4];   // (64,)
    const float* h2 = (const float*)d_in[5];   // (256,)
    plrnn_kernel<<<NCTA, NTHR>>>(X, A, W1, W2, h1, h2, (float*)d_out);
}

// round 5
// speedup vs baseline: 1.3385x; 1.3385x over previous
#include <cuda_runtime.h>
#include <math.h>

#define T_LEN 1024
#define DX    32
#define DZ    64
#define DY    256
#define BB    4
#define NCTA  128
#define NTHR  512
#define ALPHA 0.125f
#define QP    20                 // padded quarter-k stride in szfB rows (banks: 20kq%32 = {0,20,8,28})
#define ZROW  (4 * QP)           // 80 floats per szfB batch row
#define HROW  272                // shB row stride: m=136%16=8 -> GEMM1 STS is minimal 2-wf

// Packed fp32x2 FMA (Blackwell sm_103a): d = a*b + c elementwise on 64-bit pairs.
__device__ __forceinline__ float2 ffma2(float2 a, float2 b, float2 c) {
    unsigned long long au = *reinterpret_cast<unsigned long long*>(&a);
    unsigned long long bu = *reinterpret_cast<unsigned long long*>(&b);
    unsigned long long cu = *reinterpret_cast<unsigned long long*>(&c);
    unsigned long long du;
    asm("fma.rn.f32x2 %0, %1, %2, %3;" : "=l"(du) : "l"(au), "l"(bu), "l"(cu));
    return *reinterpret_cast<float2*>(&du);
}

__global__ __launch_bounds__(NTHR, 1)
void plrnn_kernel(const float* __restrict__ X,
                  const float* __restrict__ A,
                  const float* __restrict__ W1,   // (dz, dy) row-major
                  const float* __restrict__ W2,   // (dy, dz) row-major
                  const float* __restrict__ h1,
                  const float* __restrict__ h2,
                  float* __restrict__ out)        // (B, T, dx)
{
    __shared__ float szfB[BB][ZROW];         // [b][20*(k>>4) + (k&15)] zf, padded quarters
    __shared__ float shB [BB][HROW];         // [b][y] hidden (stride 272)
    __shared__ float sPart[16][BB][DZ];      // [ychunk][b][z] partials

    const int t = threadIdx.x;

    // state / reduce role (threads 0..255 own one (b,z) state each)
    const int z   = t & 63;
    const int b   = (t >> 6) & 3;
    const int bg  = blockIdx.x * BB + b;
    const int zsl = QP * (z >> 4) + (z & 15);   // padded szfB slot

    // GEMM1 role: 2 consecutive y, one quarter-k, all 4 batches
    const int q2 = t >> 2;                   // 0..127
    const int y0 = 2 * q2;
    const int kq = t & 3;                    // quarter-k id; shfl quad = lanes t^1,t^2
    const int kb = QP * kq;                  // padded base in szfB row

    // GEMM2 role: 2 consecutive z, one 16-wide y chunk, all 4 batches
    const int zg0 = 2 * (t & 31);
    const int g16 = t >> 5;                  // 0..15

    // ---- weights in registers, natural (even,odd) float2 pairs ----
    float2 w2a[8], w2b[8];                   // W2 rows y0/y0+1, k in [16*kq, +16)
#pragma unroll
    for (int p = 0; p < 8; ++p) {
        w2a[p] = *reinterpret_cast<const float2*>(&W2[(size_t)y0 * DZ + 16 * kq + 2 * p]);
        w2b[p] = *reinterpret_cast<const float2*>(&W2[(size_t)(y0 + 1) * DZ + 16 * kq + 2 * p]);
    }
    float2 w1a[8], w1b[8];                   // W1 rows zg0/zg0+1, y in [16*g16, +16)
#pragma unroll
    for (int p = 0; p < 8; ++p) {
        w1a[p] = *reinterpret_cast<const float2*>(&W1[(size_t)zg0 * DY + 16 * g16 + 2 * p]);
        w1b[p] = *reinterpret_cast<const float2*>(&W1[(size_t)(zg0 + 1) * DY + 16 * g16 + 2 * p]);
    }
    const float2 h2v = *reinterpret_cast<const float2*>(&h2[y0]);
    const float  Az  = A[z];
    const float  h1z = h1[z];

    const float* Xb = X   + (size_t)bg * T_LEN * DX;
    float*       Ob = out + (size_t)bg * T_LEN * DX;

    // ---- z0 (state owners): first dx dims forced alpha=1, rest 0 ----
    float zcur = 0.0f, x_next = 0.0f;
    if (t < 256 && z < DX) {
        float x0 = Xb[z];
        zcur   = (x0 != x0) ? 0.0f : x0;     // NaN -> keep 0
        x_next = x0;                          // step-0 forcing reuses X[:,0]
    }

    for (int step = 0; step < T_LEN; ++step) {
        // ---- phase 0: teacher forcing + publish zf (state owners only) ----
        if (t < 256) {
            float zf;
            if (z < DX) {                     // warp-uniform branch
                float x = x_next;
                zf = (x != x) ? zcur : fmaf(ALPHA, x, (1.0f - ALPHA) * zcur);
                if (step + 1 < T_LEN)
                    x_next = Xb[(size_t)(step + 1) * DX + z];
            } else {
                zf = zcur;
            }
            zcur = zf;                        // value used by A*zf later
            szfB[b][zsl] = zf;
        }
        __syncthreads();                      // B1: zf ready

        // ---- GEMM1 (quarter-k split): partials for (y0,y0+1) x 4 batches ----
        {
            float2 a0[BB], a1[BB];
#pragma unroll
            for (int bb = 0; bb < BB; ++bb) { a0[bb] = make_float2(0.f, 0.f);
                                              a1[bb] = make_float2(0.f, 0.f); }
#pragma unroll
            for (int j = 0; j < 4; ++j) {
#pragma unroll
                for (int bb = 0; bb < BB; ++bb) {
                    float4 v = *reinterpret_cast<const float4*>(&szfB[bb][kb + 4 * j]);
                    float2 lo = make_float2(v.x, v.y), hi = make_float2(v.z, v.w);
                    a0[bb] = ffma2(w2a[2 * j],     lo, a0[bb]);
                    a0[bb] = ffma2(w2a[2 * j + 1], hi, a0[bb]);
                    a1[bb] = ffma2(w2b[2 * j],     lo, a1[bb]);
                    a1[bb] = ffma2(w2b[2 * j + 1], hi, a1[bb]);
                }
            }
            // combine the 4 k-quarters within the lane quad
            float s0[BB], s1[BB];
#pragma unroll
            for (int bb = 0; bb < BB; ++bb) {
                s0[bb] = a0[bb].x + a0[bb].y;
                s1[bb] = a1[bb].x + a1[bb].y;
                s0[bb] += __shfl_xor_sync(0xffffffffu, s0[bb], 1);
                s1[bb] += __shfl_xor_sync(0xffffffffu, s1[bb], 1);
                s0[bb] += __shfl_xor_sync(0xffffffffu, s0[bb], 2);
                s1[bb] += __shfl_xor_sync(0xffffffffu, s1[bb], 2);
            }
            // lane kq stores batch kq; stride 272 -> exactly 2 wavefronts (minimum)
            float2 hv;
            hv.x = fmaxf(s0[kq] + h2v.x, 0.0f);
            hv.y = fmaxf(s1[kq] + h2v.y, 0.0f);
            *reinterpret_cast<float2*>(&shB[kq][y0]) = hv;
        }
        __syncthreads();                      // B2: hidden ready

        // ---- GEMM2: part[g16][b][zg0..+1] over 16-wide y chunk ----
        {
            float2 c0[BB], c1[BB];
#pragma unroll
            for (int bb = 0; bb < BB; ++bb) { c0[bb] = make_float2(0.f, 0.f);
                                              c1[bb] = make_float2(0.f, 0.f); }
#pragma unroll
            for (int yq = 0; yq < 4; ++yq) {
#pragma unroll
                for (int bb = 0; bb < BB; ++bb) {
                    // warp-uniform address -> broadcast, 1 wavefront
                    float4 hv = *reinterpret_cast<const float4*>(&shB[bb][16 * g16 + 4 * yq]);
                    float2 lo = make_float2(hv.x, hv.y), hi = make_float2(hv.z, hv.w);
                    c0[bb] = ffma2(w1a[2 * yq],     lo, c0[bb]);
                    c0[bb] = ffma2(w1a[2 * yq + 1], hi, c0[bb]);
                    c1[bb] = ffma2(w1b[2 * yq],     lo, c1[bb]);
                    c1[bb] = ffma2(w1b[2 * yq + 1], hi, c1[bb]);
                }
            }
#pragma unroll
            for (int bb = 0; bb < BB; ++bb) {
                float2 pr;
                pr.x = c0[bb].x + c0[bb].y;   // z = zg0
                pr.y = c1[bb].x + c1[bb].y;   // z = zg0+1
                *reinterpret_cast<float2*>(&sPart[g16][bb][zg0]) = pr;   // 2-wf min
            }
        }
        __syncthreads();                      // B3: partials ready

        // ---- reduce 16 chunks + state update + output (state owners) ----
        if (t < 256) {
            float s = 0.0f;
#pragma unroll
            for (int g = 0; g < 16; ++g) s += sPart[g][b][z];   // banks=z%32: 1 wf each
            float znew = fmaf(Az, zcur, s + h1z);
            zcur = znew;
            if (z < DX)
                Ob[(size_t)step * DX + z] = znew;   // coalesced
        }
    }
}

extern "C" void kernel_launch(void* const* d_in, const int* in_sizes, int n_in,
                              void* d_out, int out_size)
{
    const float* X  = (const float*)d_in[0];   // (512, 1024, 32)
    const float* A  = (const float*)d_in[1];   // (64,)
    const float* W1 = (const float*)d_in[2];   // (64, 256)
    const float* W2 = (const float*)d_in[3];   // (256, 64)
    const float* h1 = (const float*)d_in[4];   // (64,)
    const float* h2 = (const float*)d_in[5];   // (256,)
    plrnn_kernel<<<NCTA, NTHR>>>(X, A, W1, W2, h1, h2, (float*)d_out);
}

// round 6
// speedup vs baseline: 1.4054x; 1.0500x over previous
#include <cuda_runtime.h>
#include <math.h>

#define T_LEN 1024
#define DX    32
#define DZ    64
#define DY    256
#define BB    4
#define NCTA  128
#define NTHR  256
#define ALPHA 0.125f
#define ZROW  68                 // szfB row pad: batch rows on disjoint 16B bank-quads
#define HROW  264                // shB row pad

// Packed fp32x2 FMA (Blackwell sm_103a): d = a*b + c elementwise on 64-bit pairs.
__device__ __forceinline__ float2 ffma2(float2 a, float2 b, float2 c) {
    unsigned long long au = *reinterpret_cast<unsigned long long*>(&a);
    unsigned long long bu = *reinterpret_cast<unsigned long long*>(&b);
    unsigned long long cu = *reinterpret_cast<unsigned long long*>(&c);
    unsigned long long du;
    asm("fma.rn.f32x2 %0, %1, %2, %3;" : "=l"(du) : "l"(au), "l"(bu), "l"(cu));
    return *reinterpret_cast<float2*>(&du);
}

__global__ __launch_bounds__(NTHR, 1)
void plrnn_kernel(const float* __restrict__ X,
                  const float* __restrict__ A,
                  const float* __restrict__ W1,   // (dz, dy) row-major
                  const float* __restrict__ W2,   // (dy, dz) row-major
                  const float* __restrict__ h1,
                  const float* __restrict__ h2,
                  float* __restrict__ out)        // (B, T, dx)
{
    __shared__ float szfB[BB][ZROW];         // [b][k] zf (padded rows)
    __shared__ float shB [BB][HROW];         // [b][y] hidden (padded rows)
    __shared__ float sPart[8][BB][DZ];       // [ygroup][b][z] partials

    const int t = threadIdx.x;

    // state / reduce role: thread owns (b, z)
    const int z  = t & 63;
    const int b  = t >> 6;
    const int bg = blockIdx.x * BB + b;

    // GEMM1 role: 2 consecutive y, FULL k=64, one batch-half (2 batches)
    const int y0 = 2 * (t >> 1);             // 0..254 step 2
    const int bh = t & 1;
    const int b0 = 2 * bh, b1 = 2 * bh + 1;

    // GEMM2 role: 2 consecutive z, one 32-wide y group, all 4 batches
    const int zg0 = 2 * (t & 31);
    const int g8  = t >> 5;                  // 0..7

    // ---- weights in registers, natural (even,odd) float2 pairs (no dup) ----
    float2 w2a[32], w2b[32];                 // W2 full rows y0, y0+1 (k = 0..63)
#pragma unroll
    for (int p = 0; p < 32; ++p) {
        w2a[p] = *reinterpret_cast<const float2*>(&W2[(size_t)y0 * DZ + 2 * p]);
        w2b[p] = *reinterpret_cast<const float2*>(&W2[(size_t)(y0 + 1) * DZ + 2 * p]);
    }
    float2 w1a[16], w1b[16];                 // W1 rows zg0/zg0+1, y in [32*g8, +32)
#pragma unroll
    for (int p = 0; p < 16; ++p) {
        w1a[p] = *reinterpret_cast<const float2*>(&W1[(size_t)zg0 * DY + 32 * g8 + 2 * p]);
        w1b[p] = *reinterpret_cast<const float2*>(&W1[(size_t)(zg0 + 1) * DY + 32 * g8 + 2 * p]);
    }
    const float2 h2v = *reinterpret_cast<const float2*>(&h2[y0]);
    const float  Az  = A[z];
    const float  h1z = h1[z];

    const float* Xb = X   + (size_t)bg * T_LEN * DX;
    float*       Ob = out + (size_t)bg * T_LEN * DX;

    // ---- z0: first dx dims forced with alpha=1, rest zero ----
    float zcur = 0.0f, x_next = 0.0f;
    if (z < DX) {
        float x0 = Xb[z];
        zcur   = (x0 != x0) ? 0.0f : x0;     // NaN -> keep 0
        x_next = x0;                          // step-0 forcing reuses X[:,0]
    }

    for (int step = 0; step < T_LEN; ++step) {
        // ---- phase 0: teacher forcing + publish zf ----
        float zf;
        if (z < DX) {                         // warp-uniform branch
            float x = x_next;
            zf = (x != x) ? zcur : fmaf(ALPHA, x, (1.0f - ALPHA) * zcur);
            if (step + 1 < T_LEN)
                x_next = Xb[(size_t)(step + 1) * DX + z];
        } else {
            zf = zcur;
        }
        szfB[b][z] = zf;                      // 1 wf (banks 4b+z distinct/warp)
        __syncthreads();                      // B1: zf ready

        // ---- GEMM1 (full k, no shuffles): (y0,y0+1) x (b0,b1) ----
        {
            float2 a00 = {0.f, 0.f}, a01 = {0.f, 0.f};
            float2 a10 = {0.f, 0.f}, a11 = {0.f, 0.f};
#pragma unroll
            for (int j = 0; j < 16; ++j) {
                float4 v0 = *reinterpret_cast<const float4*>(&szfB[b0][4 * j]);
                float4 v1 = *reinterpret_cast<const float4*>(&szfB[b1][4 * j]);
                float2 lo0 = make_float2(v0.x, v0.y), hi0 = make_float2(v0.z, v0.w);
                float2 lo1 = make_float2(v1.x, v1.y), hi1 = make_float2(v1.z, v1.w);
                a00 = ffma2(w2a[2 * j],     lo0, a00);
                a00 = ffma2(w2a[2 * j + 1], hi0, a00);
                a01 = ffma2(w2a[2 * j],     lo1, a01);
                a01 = ffma2(w2a[2 * j + 1], hi1, a01);
                a10 = ffma2(w2b[2 * j],     lo0, a10);
                a10 = ffma2(w2b[2 * j + 1], hi0, a10);
                a11 = ffma2(w2b[2 * j],     lo1, a11);
                a11 = ffma2(w2b[2 * j + 1], hi1, a11);
            }
            float2 s0, s1;                     // (y0,y1) hidden for b0 / b1
            s0.x = fmaxf(a00.x + a00.y + h2v.x, 0.0f);
            s0.y = fmaxf(a10.x + a10.y + h2v.y, 0.0f);
            s1.x = fmaxf(a01.x + a01.y + h2v.x, 0.0f);
            s1.y = fmaxf(a11.x + a11.y + h2v.y, 0.0f);
            *reinterpret_cast<float2*>(&shB[b0][y0]) = s0;   // STS.64 (2 wf min)
            *reinterpret_cast<float2*>(&shB[b1][y0]) = s1;
        }
        __syncthreads();                      // B2: hidden ready

        // ---- GEMM2: part[g8][b][zg0..+1] over 32-wide y group ----
        {
            float2 c0[BB], c1[BB];
#pragma unroll
            for (int bb = 0; bb < BB; ++bb) { c0[bb] = make_float2(0.f, 0.f);
                                              c1[bb] = make_float2(0.f, 0.f); }
#pragma unroll
            for (int yq = 0; yq < 8; ++yq) {
#pragma unroll
                for (int bb = 0; bb < BB; ++bb) {
                    // warp-uniform address -> broadcast
                    float4 hv = *reinterpret_cast<const float4*>(&shB[bb][32 * g8 + 4 * yq]);
                    float2 lo = make_float2(hv.x, hv.y), hi = make_float2(hv.z, hv.w);
                    c0[bb] = ffma2(w1a[2 * yq],     lo, c0[bb]);
                    c0[bb] = ffma2(w1a[2 * yq + 1], hi, c0[bb]);
                    c1[bb] = ffma2(w1b[2 * yq],     lo, c1[bb]);
                    c1[bb] = ffma2(w1b[2 * yq + 1], hi, c1[bb]);
                }
            }
#pragma unroll
            for (int bb = 0; bb < BB; ++bb) {
                float2 pr;
                pr.x = c0[bb].x + c0[bb].y;   // z = zg0
                pr.y = c1[bb].x + c1[bb].y;   // z = zg0+1
                *reinterpret_cast<float2*>(&sPart[g8][bb][zg0]) = pr;   // 2 wf min
            }
        }
        __syncthreads();                      // B3: partials ready

        // ---- reduce 8 groups + state update + output ----
        {
            float s = 0.0f;
#pragma unroll
            for (int g = 0; g < 8; ++g) s += sPart[g][b][z];   // 1 wf each
            float znew = fmaf(Az, zf, s + h1z);
            zcur = znew;
            if (z < DX)
                Ob[(size_t)step * DX + z] = znew;   // coalesced
        }
    }
}

extern "C" void kernel_launch(void* const* d_in, const int* in_sizes, int n_in,
                              void* d_out, int out_size)
{
    const float* X  = (const float*)d_in[0];   // (512, 1024, 32)
    const float* A  = (const float*)d_in[1];   // (64,)
    const float* W1 = (const float*)d_in[2];   // (64, 256)
    const float* W2 = (const float*)d_in[3];   // (256, 64)
    const float* h1 = (const float*)d_in[4];   // (64,)
    const float* h2 = (const float*)d_in[5];   // (256,)
    plrnn_kernel<<<NCTA, NTHR>>>(X, A, W1, W2, h1, h2, (float*)d_out);
}

// round 7
// speedup vs baseline: 1.4548x; 1.0351x over previous
#include <cuda_runtime.h>
#include <math.h>

#define T_LEN 1024
#define DX    32
#define DZ    64
#define DY    256
#define BB    4
#define NCTA  128
#define NTHR  256
#define ALPHA 0.125f
#define KHPAD 36                 // padded k-half stride in szfB rows
#define ZROW  (2 * KHPAD)        // 72 floats per szfB batch row
#define HROW  264                // shB row stride (mod 32 == 8 -> 2-wf min STS)

// Packed fp32x2 FMA (Blackwell sm_103a): d = a*b + c elementwise on 64-bit pairs.
__device__ __forceinline__ float2 ffma2(float2 a, float2 b, float2 c) {
    unsigned long long au = *reinterpret_cast<unsigned long long*>(&a);
    unsigned long long bu = *reinterpret_cast<unsigned long long*>(&b);
    unsigned long long cu = *reinterpret_cast<unsigned long long*>(&c);
    unsigned long long du;
    asm("fma.rn.f32x2 %0, %1, %2, %3;" : "=l"(du) : "l"(au), "l"(bu), "l"(cu));
    return *reinterpret_cast<float2*>(&du);
}

__global__ __launch_bounds__(NTHR, 1)
void plrnn_kernel(const float* __restrict__ X,
                  const float* __restrict__ A,
                  const float* __restrict__ W1,   // (dz, dy) row-major
                  const float* __restrict__ W2,   // (dy, dz) row-major
                  const float* __restrict__ h1,
                  const float* __restrict__ h2,
                  float* __restrict__ out)        // (B, T, dx)
{
    __shared__ float szfB[BB][ZROW];         // [b][36*(k>>5) + (k&31)] zf
    __shared__ float shB [BB][HROW];         // [b][y] hidden
    __shared__ float sPart[8][BB][DZ];       // [ygroup][b][z] partials

    const int t = threadIdx.x;

    // state / reduce role: thread owns (b, z)
    const int z   = t & 63;
    const int b   = t >> 6;
    const int bg  = blockIdx.x * BB + b;
    const int zsl = (z >> 5) * KHPAD + (z & 31);

    // GEMM1 role: 2 consecutive y, one k-half; warp w covers y in [32w, 32w+32)
    const int y0 = 2 * (t >> 1);
    const int kh = t & 1;                    // k-half; partner lane = t^1
    const int kb = kh * KHPAD;

    // GEMM2 role: 2 consecutive z, y chunk [32w, 32w+32) — SAME warp as producer
    const int zg0 = 2 * (t & 31);
    const int g8  = t >> 5;                  // == warp id

    // ---- weights in registers, natural (even,odd) float2 pairs (no dup) ----
    float2 w2a[16], w2b[16];                 // W2 rows y0/y0+1, this k-half
#pragma unroll
    for (int p = 0; p < 16; ++p) {
        w2a[p] = *reinterpret_cast<const float2*>(&W2[(size_t)y0 * DZ + 32 * kh + 2 * p]);
        w2b[p] = *reinterpret_cast<const float2*>(&W2[(size_t)(y0 + 1) * DZ + 32 * kh + 2 * p]);
    }
    float2 w1a[16], w1b[16];                 // W1 rows zg0/zg0+1, y in [32*g8, +32)
#pragma unroll
    for (int p = 0; p < 16; ++p) {
        w1a[p] = *reinterpret_cast<const float2*>(&W1[(size_t)zg0 * DY + 32 * g8 + 2 * p]);
        w1b[p] = *reinterpret_cast<const float2*>(&W1[(size_t)(zg0 + 1) * DY + 32 * g8 + 2 * p]);
    }
    const float2 h2v = *reinterpret_cast<const float2*>(&h2[y0]);
    const float  Az  = A[z];
    const float  h1z = h1[z];

    const float* Xb = X   + (size_t)bg * T_LEN * DX;
    float*       Ob = out + (size_t)bg * T_LEN * DX;

    // ---- z0: first dx dims forced with alpha=1, rest zero ----
    float zcur = 0.0f, x_next = 0.0f;
    if (z < DX) {
        float x0 = Xb[z];
        zcur   = (x0 != x0) ? 0.0f : x0;     // NaN -> keep 0
        x_next = x0;                          // step-0 forcing reuses X[:,0]
    }

    for (int step = 0; step < T_LEN; ++step) {
        // ---- phase 0: teacher forcing + publish zf ----
        float zf;
        if (z < DX) {                         // warp-uniform (z spans 32/warp)
            float x = x_next;
            zf = (x != x) ? zcur : fmaf(ALPHA, x, (1.0f - ALPHA) * zcur);
            if (step + 1 < T_LEN)
                x_next = Xb[(size_t)(step + 1) * DX + z];
        } else {
            zf = zcur;
        }
        szfB[b][zsl] = zf;                    // 1 wf
        __syncthreads();                      // B1: zf ready (cross-warp)

        // ---- GEMM1 (k-half split): partials for (y0,y0+1) x 4 batches ----
        {
            float2 a0[BB], a1[BB];
#pragma unroll
            for (int bb = 0; bb < BB; ++bb) { a0[bb] = make_float2(0.f, 0.f);
                                              a1[bb] = make_float2(0.f, 0.f); }
#pragma unroll
            for (int j = 0; j < 8; ++j) {
#pragma unroll
                for (int bb = 0; bb < BB; ++bb) {
                    float4 v = *reinterpret_cast<const float4*>(&szfB[bb][kb + 4 * j]);
                    float2 lo = make_float2(v.x, v.y), hi = make_float2(v.z, v.w);
                    a0[bb] = ffma2(w2a[2 * j],     lo, a0[bb]);
                    a0[bb] = ffma2(w2a[2 * j + 1], hi, a0[bb]);
                    a1[bb] = ffma2(w2b[2 * j],     lo, a1[bb]);
                    a1[bb] = ffma2(w2b[2 * j + 1], hi, a1[bb]);
                }
            }
            // raw per-k-half sums S[y][bb]
            float S0[BB], S1[BB];
#pragma unroll
            for (int bb = 0; bb < BB; ++bb) {
                S0[bb] = a0[bb].x + a0[bb].y;
                S1[bb] = a1[bb].x + a1[bb].y;
            }
            // payload-split combine: 4 shfls total. Lane kh keeps batches
            // {2kh, 2kh+1}; sends the other half to its partner (lane^1).
            const bool hi = (kh != 0);
#pragma unroll
            for (int u = 0; u < 2; ++u) {
                float send0 = hi ? S0[u] : S0[2 + u];
                float keep0 = hi ? S0[2 + u] : S0[u];
                float send1 = hi ? S1[u] : S1[2 + u];
                float keep1 = hi ? S1[2 + u] : S1[u];
                float f0 = keep0 + __shfl_xor_sync(0xffffffffu, send0, 1);
                float f1 = keep1 + __shfl_xor_sync(0xffffffffu, send1, 1);
                float2 hv;
                hv.x = fmaxf(f0 + h2v.x, 0.0f);   // (y0, bsel)
                hv.y = fmaxf(f1 + h2v.y, 0.0f);   // (y1, bsel)
                *reinterpret_cast<float2*>(&shB[2 * kh + u][y0]) = hv;  // 2-wf min
            }
        }
        __syncwarp();                         // producer == consumer warp: no CTA barrier

        // ---- GEMM2: part[g8][b][zg0..+1] over own 32-wide y chunk ----
        {
            float2 c0[BB], c1[BB];
#pragma unroll
            for (int bb = 0; bb < BB; ++bb) { c0[bb] = make_float2(0.f, 0.f);
                                              c1[bb] = make_float2(0.f, 0.f); }
#pragma unroll
            for (int yq = 0; yq < 8; ++yq) {
#pragma unroll
                for (int bb = 0; bb < BB; ++bb) {
                    // warp-uniform address -> broadcast, 1 wf
                    float4 hv = *reinterpret_cast<const float4*>(&shB[bb][32 * g8 + 4 * yq]);
                    float2 lo = make_float2(hv.x, hv.y), hi2 = make_float2(hv.z, hv.w);
                    c0[bb] = ffma2(w1a[2 * yq],     lo,  c0[bb]);
                    c0[bb] = ffma2(w1a[2 * yq + 1], hi2, c0[bb]);
                    c1[bb] = ffma2(w1b[2 * yq],     lo,  c1[bb]);
                    c1[bb] = ffma2(w1b[2 * yq + 1], hi2, c1[bb]);
                }
            }
#pragma unroll
            for (int bb = 0; bb < BB; ++bb) {
                float2 pr;
                pr.x = c0[bb].x + c0[bb].y;   // z = zg0
                pr.y = c1[bb].x + c1[bb].y;   // z = zg0+1
                *reinterpret_cast<float2*>(&sPart[g8][bb][zg0]) = pr;   // 2-wf min
            }
        }
        __syncthreads();                      // B3: partials ready (cross-warp)

        // ---- reduce 8 groups + state update + output ----
        {
            float s = 0.0f;
#pragma unroll
            for (int g = 0; g < 8; ++g) s += sPart[g][b][z];   // 1 wf each
            float znew = fmaf(Az, zf, s + h1z);
            zcur = znew;
            if (z < DX)
                Ob[(size_t)step * DX + z] = znew;   // coalesced
        }
    }
}

extern "C" void kernel_launch(void* const* d_in, const int* in_sizes, int n_in,
                              void* d_out, int out_size)
{
    const float* X  = (const float*)d_in[0];   // (512, 1024, 32)
    const float* A  = (const float*)d_in[1];   // (64,)
    const float* W1 = (const float*)d_in[2];   // (64, 256)
    const float* W2 = (const float*)d_in[3];   // (256, 64)
    const float* h1 = (const float*)d_in[4];   // (64,)
    const float* h2 = (const float*)d_in[5];   // (256,)
    plrnn_kernel<<<NCTA, NTHR>>>(X, A, W1, W2, h1, h2, (float*)d_out);
}